// round 11
// baseline (speedup 1.0000x reference)
#include <cuda_runtime.h>

#define M 512
#define K1_GRID 592    // 4 CTAs/SM x 148 SMs -> co-residency guaranteed (barrier-safe)
#define K2_GRID 608

// Scratch (__device__ globals; zero-init at load; cleanup-at-end for replays)
__device__ float    g_q[131072 * 4]; // quarter-row dot partials (overwritten each replay)
__device__ float    g_v1r[4][M];     // W^T a1 replicas (atomic accum; zeroed by K1 last CTA)
__device__ float    g_v2r[4][M];     // W^T a2 replicas (zeroed by K1 last CTA)
__device__ float    g_colsum[M];     // column sums (zeroed by K1 last CTA)
__device__ float    g_scal[4];       // [0]=c1+c2 (store), [1]=C (store), [2]=Z (zeroed)
__device__ unsigned g_cA, g_relA;    // K1 start barrier (reset by K1 last CTA)
__device__ unsigned g_cnt1, g_cnt2;

// ---------------------------------------------------------------------------
// K1: [prep: CTAs 0..255 -> v replicas, CTA 256 -> b-dots + zero out]
//     -> grid barrier (all 592 CTAs co-resident by construction)
//     -> FLAT ascending stream of x: colsum + quarter-row dot partials.
//     -> last CTA: C = c1+c2 + (colsum.v2)/K ; cleanup.
// ---------------------------------------------------------------------------
__global__ __launch_bounds__(256, 4) void mhi_k1(const float* __restrict__ x,
                                                 const float* __restrict__ W,
                                                 const float* __restrict__ b,
                                                 const float* __restrict__ a,
                                                 float* __restrict__ out, int K) {
    int tid  = threadIdx.x;
    int lane = tid & 31, w = tid >> 5;
    int bid  = blockIdx.x;

    // ---- prep portion ----
    if (bid < 256) {
        int rg  = tid >> 7;          // 0/1: which of the two W rows
        int c4  = tid & 127;         // float4 column index
        int row = bid * 2 + rg;
        float4 w4 = reinterpret_cast<const float4*>(W)[row * 128 + c4];
        float A1 = __ldg(a + row);
        float A2 = __ldg(a + M + row);
        float4 s1 = {A1*w4.x, A1*w4.y, A1*w4.z, A1*w4.w};
        float4 s2 = {A2*w4.x, A2*w4.y, A2*w4.z, A2*w4.w};
        __shared__ float4 sm1[128], sm2[128];
        if (rg == 1) { sm1[c4] = s1; sm2[c4] = s2; }
        __syncthreads();
        if (rg == 0) {
            float4 o1 = sm1[c4], o2 = sm2[c4];
            s1.x += o1.x; s1.y += o1.y; s1.z += o1.z; s1.w += o1.w;
            s2.x += o2.x; s2.y += o2.y; s2.z += o2.z; s2.w += o2.w;
            int rep = bid & 3;
            int j = c4 * 4;
            atomicAdd(&g_v1r[rep][j + 0], s1.x); atomicAdd(&g_v1r[rep][j + 1], s1.y);
            atomicAdd(&g_v1r[rep][j + 2], s1.z); atomicAdd(&g_v1r[rep][j + 3], s1.w);
            atomicAdd(&g_v2r[rep][j + 0], s2.x); atomicAdd(&g_v2r[rep][j + 1], s2.y);
            atomicAdd(&g_v2r[rep][j + 2], s2.z); atomicAdd(&g_v2r[rep][j + 3], s2.w);
        }
    } else if (bid == 256) {
        out[tid]       = 0.f;   // d_out is poisoned: zero before K2's atomics
        out[tid + 256] = 0.f;
        float p1 = 0.f, p2 = 0.f;
        for (int i = tid; i < M; i += 256) {
            p1 += b[i] * a[i];
            p2 += b[i] * a[M + i];
        }
        #pragma unroll
        for (int o = 16; o; o >>= 1) {
            p1 += __shfl_xor_sync(0xFFFFFFFFu, p1, o);
            p2 += __shfl_xor_sync(0xFFFFFFFFu, p2, o);
        }
        __shared__ float rb[16];
        if (lane == 0) { rb[w] = p1; rb[8 + w] = p2; }
        __syncthreads();
        if (tid == 0) {
            float s = 0.f;
            #pragma unroll
            for (int q = 0; q < 16; q++) s += rb[q];
            g_scal[0] = s;      // c1 + c2
        }
    }

    // ---- grid barrier: v1 must be complete before the stream ----
    __threadfence();
    __syncthreads();
    if (tid == 0) {
        if (atomicAdd(&g_cA, 1u) == K1_GRID - 1) {
            atomicExch(&g_relA, 1u);
        } else {
            while (atomicAdd(&g_relA, 0u) == 0u) __nanosleep(64);
        }
    }
    __syncthreads();
    __threadfence();

    // ---- flat ascending stream: colsum + quarter-row dot partials ----
    __shared__ float scol[M];
    for (int j = tid; j < M; j += 256) scol[j] = 0.f;
    __syncthreads();

    int c4 = tid & 127;
    float4 v4;
    {
        const float4* r0 = reinterpret_cast<const float4*>(g_v1r[0]);
        const float4* r1 = reinterpret_cast<const float4*>(g_v1r[1]);
        const float4* r2 = reinterpret_cast<const float4*>(g_v1r[2]);
        const float4* r3 = reinterpret_cast<const float4*>(g_v1r[3]);
        float4 q0 = r0[c4], q1 = r1[c4], q2 = r2[c4], q3 = r3[c4];
        v4 = make_float4(q0.x+q1.x+q2.x+q3.x, q0.y+q1.y+q2.y+q3.y,
                         q0.z+q1.z+q2.z+q3.z, q0.w+q1.w+q2.w+q3.w);
    }

    const float4* X4 = reinterpret_cast<const float4*>(x);
    int N4     = K * 128;
    int stride = K1_GRID * 256;     // 151552, divisible by 128
    int idx    = bid * 256 + tid;
    float4 acc = {0, 0, 0, 0};
    for (; idx + 3 * stride < N4; idx += 4 * stride) {
        float4 p0 = X4[idx];
        float4 p1 = X4[idx + stride];
        float4 p2 = X4[idx + 2 * stride];
        float4 p3 = X4[idx + 3 * stride];
        float d0 = p0.x*v4.x + p0.y*v4.y + p0.z*v4.z + p0.w*v4.w;
        float d1 = p1.x*v4.x + p1.y*v4.y + p1.z*v4.z + p1.w*v4.w;
        float d2 = p2.x*v4.x + p2.y*v4.y + p2.z*v4.z + p2.w*v4.w;
        float d3 = p3.x*v4.x + p3.y*v4.y + p3.z*v4.z + p3.w*v4.w;
        #pragma unroll
        for (int o = 16; o; o >>= 1) {
            d0 += __shfl_xor_sync(0xFFFFFFFFu, d0, o);
            d1 += __shfl_xor_sync(0xFFFFFFFFu, d1, o);
            d2 += __shfl_xor_sync(0xFFFFFFFFu, d2, o);
            d3 += __shfl_xor_sync(0xFFFFFFFFu, d3, o);
        }
        if (lane == 0) {
            g_q[idx >> 5]                = d0;
            g_q[(idx + stride) >> 5]     = d1;
            g_q[(idx + 2 * stride) >> 5] = d2;
            g_q[(idx + 3 * stride) >> 5] = d3;
        }
        acc.x += (p0.x + p1.x) + (p2.x + p3.x);
        acc.y += (p0.y + p1.y) + (p2.y + p3.y);
        acc.z += (p0.z + p1.z) + (p2.z + p3.z);
        acc.w += (p0.w + p1.w) + (p2.w + p3.w);
    }
    for (; idx < N4; idx += stride) {
        float4 p = X4[idx];
        float d = p.x*v4.x + p.y*v4.y + p.z*v4.z + p.w*v4.w;
        #pragma unroll
        for (int o = 16; o; o >>= 1) d += __shfl_xor_sync(0xFFFFFFFFu, d, o);
        if (lane == 0) g_q[idx >> 5] = d;
        acc.x += p.x; acc.y += p.y; acc.z += p.z; acc.w += p.w;
    }
    {
        int j = c4 * 4;
        atomicAdd(&scol[j + 0], acc.x); atomicAdd(&scol[j + 1], acc.y);
        atomicAdd(&scol[j + 2], acc.z); atomicAdd(&scol[j + 3], acc.w);
    }
    __syncthreads();
    for (int j = tid; j < M; j += 256) atomicAdd(&g_colsum[j], scol[j]);

    // ---- last CTA: C; cleanup for graph replay ----
    __shared__ bool isLast;
    __threadfence();
    __syncthreads();
    if (tid == 0) isLast = (atomicAdd(&g_cnt1, 1u) == gridDim.x - 1);
    __syncthreads();
    if (isLast) {
        float p = 0.f;
        for (int j = tid; j < M; j += 256) {
            float v2j = g_v2r[0][j] + g_v2r[1][j] + g_v2r[2][j] + g_v2r[3][j];
            p += g_colsum[j] * v2j;
        }
        #pragma unroll
        for (int o = 16; o; o >>= 1) p += __shfl_xor_sync(0xFFFFFFFFu, p, o);
        __shared__ float sp[8];
        if (lane == 0) sp[w] = p;
        __syncthreads();
        for (int j = tid; j < M; j += 256) {     // cleanup accumulators
            g_colsum[j] = 0.f;
            g_v1r[0][j] = 0.f; g_v1r[1][j] = 0.f; g_v1r[2][j] = 0.f; g_v1r[3][j] = 0.f;
            g_v2r[0][j] = 0.f; g_v2r[1][j] = 0.f; g_v2r[2][j] = 0.f; g_v2r[3][j] = 0.f;
        }
        if (tid == 0) {
            float s = 0.f;
            #pragma unroll
            for (int q = 0; q < 8; q++) s += sp[q];
            g_scal[1] = g_scal[0] + s * (1.0f / (float)K);   // C
            g_cnt1 = 0u;
            g_cA = 0u; g_relA = 0u;              // reset barrier for next replay
        }
    }
}

// ---------------------------------------------------------------------------
// K2 (flat DESCENDING stream; top of x is L2-hot from K1): 8-DEEP unroll
// (8 independent LDG.128 + 8 uniform q-loads in flight per thread) to break
// the latency cap seen at 4-deep. w = exp(max(t + C, 0)); acc += w * x4.
// Z counted once per row (quarter-0 warps, warp-uniform w).
// ---------------------------------------------------------------------------
__global__ __launch_bounds__(256, 4) void mhi_k2(const float* __restrict__ x,
                                                 float* __restrict__ out, int K) {
    __shared__ float scol[M];
    int tid = threadIdx.x;
    for (int j = tid; j < M; j += 256) scol[j] = 0.f;
    __syncthreads();

    float C = g_scal[1];
    int lane = tid & 31, w = tid >> 5;
    const float4* X4 = reinterpret_cast<const float4*>(x);
    const float4* Q4 = reinterpret_cast<const float4*>(g_q);
    const int stride = K2_GRID * 256;          // 155648, divisible by 128
    int N4   = K * 128;
    int base = blockIdx.x * 256 + tid;
    bool countz = (((base >> 5) & 3) == 0);    // warp-uniform: one warp per row counts Z

    float4 acc = {0, 0, 0, 0};
    float zloc = 0.f;
    int niter = (N4 - base + stride - 1) / stride;   // base < stride <= N4 always
    int idx   = base + (niter - 1) * stride;
    int it    = niter;
    for (; it >= 8; it -= 8) {
        int i0 = idx,              i1 = idx - stride,     i2 = idx - 2 * stride,
            i3 = idx - 3 * stride, i4 = idx - 4 * stride, i5 = idx - 5 * stride,
            i6 = idx - 6 * stride, i7 = idx - 7 * stride;
        // 8 independent big loads
        float4 p0 = X4[i0], p1 = X4[i1], p2 = X4[i2], p3 = X4[i3];
        float4 p4 = X4[i4], p5 = X4[i5], p6 = X4[i6], p7 = X4[i7];
        // 8 uniform 16B loads; convert to scalar w immediately (caps liveness)
        float4 q;
        q = __ldg(Q4 + (i0 >> 7)); float w0 = __expf(fmaxf((q.x+q.y)+(q.z+q.w)+C, 0.f));
        q = __ldg(Q4 + (i1 >> 7)); float w1 = __expf(fmaxf((q.x+q.y)+(q.z+q.w)+C, 0.f));
        q = __ldg(Q4 + (i2 >> 7)); float w2 = __expf(fmaxf((q.x+q.y)+(q.z+q.w)+C, 0.f));
        q = __ldg(Q4 + (i3 >> 7)); float w3 = __expf(fmaxf((q.x+q.y)+(q.z+q.w)+C, 0.f));
        q = __ldg(Q4 + (i4 >> 7)); float w4 = __expf(fmaxf((q.x+q.y)+(q.z+q.w)+C, 0.f));
        q = __ldg(Q4 + (i5 >> 7)); float w5 = __expf(fmaxf((q.x+q.y)+(q.z+q.w)+C, 0.f));
        q = __ldg(Q4 + (i6 >> 7)); float w6 = __expf(fmaxf((q.x+q.y)+(q.z+q.w)+C, 0.f));
        q = __ldg(Q4 + (i7 >> 7)); float w7 = __expf(fmaxf((q.x+q.y)+(q.z+q.w)+C, 0.f));
        acc.x += ((w0*p0.x + w1*p1.x) + (w2*p2.x + w3*p3.x))
               + ((w4*p4.x + w5*p5.x) + (w6*p6.x + w7*p7.x));
        acc.y += ((w0*p0.y + w1*p1.y) + (w2*p2.y + w3*p3.y))
               + ((w4*p4.y + w5*p5.y) + (w6*p6.y + w7*p7.y));
        acc.z += ((w0*p0.z + w1*p1.z) + (w2*p2.z + w3*p3.z))
               + ((w4*p4.z + w5*p5.z) + (w6*p6.z + w7*p7.z));
        acc.w += ((w0*p0.w + w1*p1.w) + (w2*p2.w + w3*p3.w))
               + ((w4*p4.w + w5*p5.w) + (w6*p6.w + w7*p7.w));
        if (countz) zloc += ((w0 + w1) + (w2 + w3)) + ((w4 + w5) + (w6 + w7));
        idx -= 8 * stride;
    }
    for (; it > 0; it--) {
        float4 p = X4[idx];
        float4 q = __ldg(Q4 + (idx >> 7));
        float wk = __expf(fmaxf((q.x + q.y) + (q.z + q.w) + C, 0.f));
        acc.x += wk*p.x; acc.y += wk*p.y; acc.z += wk*p.z; acc.w += wk*p.w;
        if (countz) zloc += wk;
        idx -= stride;
    }

    {
        int j = (base & 127) * 4;   // fixed column group per thread
        atomicAdd(&scol[j + 0], acc.x); atomicAdd(&scol[j + 1], acc.y);
        atomicAdd(&scol[j + 2], acc.z); atomicAdd(&scol[j + 3], acc.w);
    }
    __shared__ float zw[8];
    if (lane == 0) zw[w] = zloc;    // warp-uniform (zero for non-counting warps)
    __syncthreads();
    if (tid == 0) {
        float z = 0.f;
        #pragma unroll
        for (int q = 0; q < 8; q++) z += zw[q];
        atomicAdd(&g_scal[2], z);
    }
    for (int j = tid; j < M; j += 256) atomicAdd(&out[j], scol[j]);

    // last CTA: normalize by Z; cleanup for next graph replay
    __shared__ bool isLast;
    __threadfence();
    __syncthreads();
    if (tid == 0) isLast = (atomicAdd(&g_cnt2, 1u) == gridDim.x - 1);
    __syncthreads();
    if (isLast) {
        float invZ = 1.0f / g_scal[2];
        for (int j = tid; j < M; j += 256) out[j] *= invZ;
        if (tid == 0) { g_scal[2] = 0.f; g_cnt2 = 0u; }
    }
}

// ---------------------------------------------------------------------------
extern "C" void kernel_launch(void* const* d_in, const int* in_sizes, int n_in,
                              void* d_out, int out_size) {
    const float* x = (const float*)d_in[0];   // [K, 512]
    const float* W = (const float*)d_in[1];   // [512, 512]
    const float* b = (const float*)d_in[2];   // [512]
    const float* a = (const float*)d_in[3];   // [1024]
    float* out = (float*)d_out;               // [512]
    int K = in_sizes[0] / M;

    mhi_k1<<<K1_GRID, 256>>>(x, W, b, a, out, K);
    mhi_k2<<<K2_GRID, 256>>>(x, out, K);
}

// round 12
// speedup vs baseline: 1.2804x; 1.2804x over previous
#include <cuda_runtime.h>

#define M 512
#define K1_GRID 608    // 4 CTAs/SM
#define K2_GRID 456    // 3 CTAs/SM x 152 SMs (85-reg budget for 2-row K2)

// Scratch (__device__ globals; zero-init at load; cleanup-at-end for replays)
__device__ float    g_v1r[4][M];   // W^T a1 replicas (atomic accum; zeroed by K1 last CTA)
__device__ float    g_v2r[4][M];   // W^T a2 replicas (zeroed by K1 last CTA)
__device__ float    g_v1[M];       // final v1 (plain store by K1 last CTA)
__device__ float    g_colsum[M];   // column sums (zeroed by K1 last CTA)
__device__ float    g_scal[4];     // [0]=c1+c2 (store), [1]=C (store), [2]=Z (zeroed)
__device__ unsigned g_cnt1, g_cnt2;

// ---------------------------------------------------------------------------
// K1 (exact R7 structure): prep folded in (CTAs 0..255: W rows -> v replicas;
// CTA 256: b-dots + zero out), then ALL CTAs flat-stream x (pure read,
// 4-deep unroll) for colsum. No barrier: prep results are consumed only by
// the last CTA. Last CTA: v1 = sum(replicas); C = c1+c2 + (colsum.v2)/K.
// Ascending sweep -> tail of x stays L2-resident for K2 (descending).
// ---------------------------------------------------------------------------
__global__ __launch_bounds__(256, 4) void mhi_k1(const float* __restrict__ x,
                                                 const float* __restrict__ W,
                                                 const float* __restrict__ b,
                                                 const float* __restrict__ a,
                                                 float* __restrict__ out, int K) {
    int tid  = threadIdx.x;
    int lane = tid & 31, w = tid >> 5;
    int bid  = blockIdx.x;

    // ---- prep portion (cheap; no dependency on the streaming part) ----
    if (bid < 256) {
        int rg  = tid >> 7;          // 0/1: which of the two W rows
        int c4  = tid & 127;         // float4 column index
        int row = bid * 2 + rg;
        float4 w4 = reinterpret_cast<const float4*>(W)[row * 128 + c4];
        float A1 = __ldg(a + row);
        float A2 = __ldg(a + M + row);
        float4 s1 = {A1*w4.x, A1*w4.y, A1*w4.z, A1*w4.w};
        float4 s2 = {A2*w4.x, A2*w4.y, A2*w4.z, A2*w4.w};
        __shared__ float4 sm1[128], sm2[128];
        if (rg == 1) { sm1[c4] = s1; sm2[c4] = s2; }
        __syncthreads();
        if (rg == 0) {
            float4 o1 = sm1[c4], o2 = sm2[c4];
            s1.x += o1.x; s1.y += o1.y; s1.z += o1.z; s1.w += o1.w;
            s2.x += o2.x; s2.y += o2.y; s2.z += o2.z; s2.w += o2.w;
            int rep = bid & 3;
            int j = c4 * 4;
            atomicAdd(&g_v1r[rep][j + 0], s1.x); atomicAdd(&g_v1r[rep][j + 1], s1.y);
            atomicAdd(&g_v1r[rep][j + 2], s1.z); atomicAdd(&g_v1r[rep][j + 3], s1.w);
            atomicAdd(&g_v2r[rep][j + 0], s2.x); atomicAdd(&g_v2r[rep][j + 1], s2.y);
            atomicAdd(&g_v2r[rep][j + 2], s2.z); atomicAdd(&g_v2r[rep][j + 3], s2.w);
        }
        __syncthreads();
    } else if (bid == 256) {
        out[tid]       = 0.f;   // d_out is poisoned: zero before K2's atomics
        out[tid + 256] = 0.f;
        float p1 = 0.f, p2 = 0.f;
        for (int i = tid; i < M; i += 256) {
            p1 += b[i] * a[i];
            p2 += b[i] * a[M + i];
        }
        #pragma unroll
        for (int o = 16; o; o >>= 1) {
            p1 += __shfl_xor_sync(0xFFFFFFFFu, p1, o);
            p2 += __shfl_xor_sync(0xFFFFFFFFu, p2, o);
        }
        __shared__ float rb[16];
        if (lane == 0) { rb[w] = p1; rb[8 + w] = p2; }
        __syncthreads();
        if (tid == 0) {
            float s = 0.f;
            #pragma unroll
            for (int q = 0; q < 16; q++) s += rb[q];
            g_scal[0] = s;      // c1 + c2
        }
    }

    // ---- flat streaming colsum over x (ascending; pure read; unroll 4) ----
    __shared__ float scol[M];
    for (int j = tid; j < M; j += 256) scol[j] = 0.f;
    __syncthreads();

    const float4* X4 = reinterpret_cast<const float4*>(x);
    int N4     = K * 128;
    int stride = K1_GRID * 256;     // 155648, divisible by 128
    int idx    = bid * 256 + tid;
    float4 acc = {0, 0, 0, 0};
    for (; idx + 3 * stride < N4; idx += 4 * stride) {
        float4 p0 = X4[idx];
        float4 p1 = X4[idx + stride];
        float4 p2 = X4[idx + 2 * stride];
        float4 p3 = X4[idx + 3 * stride];
        acc.x += (p0.x + p1.x) + (p2.x + p3.x);
        acc.y += (p0.y + p1.y) + (p2.y + p3.y);
        acc.z += (p0.z + p1.z) + (p2.z + p3.z);
        acc.w += (p0.w + p1.w) + (p2.w + p3.w);
    }
    for (; idx < N4; idx += stride) {
        float4 p = X4[idx];
        acc.x += p.x; acc.y += p.y; acc.z += p.z; acc.w += p.w;
    }
    {
        int j = (tid & 127) * 4;
        atomicAdd(&scol[j + 0], acc.x); atomicAdd(&scol[j + 1], acc.y);
        atomicAdd(&scol[j + 2], acc.z); atomicAdd(&scol[j + 3], acc.w);
    }
    __syncthreads();
    for (int j = tid; j < M; j += 256) atomicAdd(&g_colsum[j], scol[j]);

    // ---- last CTA: finalize v1, compute C, cleanup for graph replay ----
    __shared__ bool isLast;
    __threadfence();
    __syncthreads();
    if (tid == 0) isLast = (atomicAdd(&g_cnt1, 1u) == gridDim.x - 1);
    __syncthreads();
    if (isLast) {
        float p = 0.f;
        for (int j = tid; j < M; j += 256) {
            float v1j = g_v1r[0][j] + g_v1r[1][j] + g_v1r[2][j] + g_v1r[3][j];
            float v2j = g_v2r[0][j] + g_v2r[1][j] + g_v2r[2][j] + g_v2r[3][j];
            g_v1[j] = v1j;                       // plain store (overwritten each replay)
            p += g_colsum[j] * v2j;
        }
        #pragma unroll
        for (int o = 16; o; o >>= 1) p += __shfl_xor_sync(0xFFFFFFFFu, p, o);
        __shared__ float sp[8];
        if (lane == 0) sp[w] = p;
        __syncthreads();
        for (int j = tid; j < M; j += 256) {     // cleanup accumulators
            g_colsum[j] = 0.f;
            g_v1r[0][j] = 0.f; g_v1r[1][j] = 0.f; g_v1r[2][j] = 0.f; g_v1r[3][j] = 0.f;
            g_v2r[0][j] = 0.f; g_v2r[1][j] = 0.f; g_v2r[2][j] = 0.f; g_v2r[3][j] = 0.f;
        }
        if (tid == 0) {
            float s = 0.f;
            #pragma unroll
            for (int q = 0; q < 8; q++) s += sp[q];
            g_scal[1] = g_scal[0] + s * (1.0f / (float)K);   // C
            g_cnt1 = 0u;
        }
    }
}

// ---------------------------------------------------------------------------
// K2 (DESCENDING pairs; top of x is L2-hot from K1): warp-per-row, TWO rows
// per iteration with v HELD IN REGISTERS (the R8 failure was in-loop smem v
// reads under a 64-reg cap). launch_bounds(256,3) -> 85-reg budget: 2 rows
// (32) + acc (16) + v (16) + misc fit without spills; 8 LDG.128 in flight
// per warp. w = exp(relu(t + C)); out += w x; Z += w.
// ---------------------------------------------------------------------------
__global__ __launch_bounds__(256, 3) void mhi_k2(const float* __restrict__ x,
                                                 float* __restrict__ out, int K) {
    __shared__ float4 sv[M / 4];
    __shared__ float  scol[M];
    int tid = threadIdx.x;
    if (tid < M / 4) sv[tid] = reinterpret_cast<const float4*>(g_v1)[tid];
    for (int j = tid; j < M; j += 256) scol[j] = 0.f;
    __syncthreads();

    float C = g_scal[1];
    int lane = tid & 31, w = tid >> 5;
    // hoist v into registers once (16 regs, loop-invariant)
    float4 v0 = sv[lane], v1 = sv[lane + 32], v2 = sv[lane + 64], v3 = sv[lane + 96];

    float4 a0 = {0,0,0,0}, a1 = a0, a2 = a0, a3 = a0;
    float zloc = 0.f;
    int gw = blockIdx.x * 8 + w;
    int nw = K2_GRID * 8;
    int P = (K + 1) >> 1;                        // row pairs
    for (int p = P - 1 - gw; p >= 0; p -= nw) {  // descending: L2-hot first
        int k = 2 * p;
        bool hasB = (k + 1) < K;
        const float4* rA = reinterpret_cast<const float4*>(x + (size_t)k * M);
        const float4* rB = reinterpret_cast<const float4*>(x + (size_t)(hasB ? k + 1 : k) * M);
        float4 x0 = rA[lane], x1 = rA[lane + 32], x2 = rA[lane + 64], x3 = rA[lane + 96];
        float4 y0 = rB[lane], y1 = rB[lane + 32], y2 = rB[lane + 64], y3 = rB[lane + 96];

        float dA = x0.x*v0.x + x0.y*v0.y + x0.z*v0.z + x0.w*v0.w
                 + x1.x*v1.x + x1.y*v1.y + x1.z*v1.z + x1.w*v1.w
                 + x2.x*v2.x + x2.y*v2.y + x2.z*v2.z + x2.w*v2.w
                 + x3.x*v3.x + x3.y*v3.y + x3.z*v3.z + x3.w*v3.w;
        float dB = y0.x*v0.x + y0.y*v0.y + y0.z*v0.z + y0.w*v0.w
                 + y1.x*v1.x + y1.y*v1.y + y1.z*v1.z + y1.w*v1.w
                 + y2.x*v2.x + y2.y*v2.y + y2.z*v2.z + y2.w*v2.w
                 + y3.x*v3.x + y3.y*v3.y + y3.z*v3.z + y3.w*v3.w;
        #pragma unroll
        for (int o = 16; o; o >>= 1) {
            dA += __shfl_xor_sync(0xFFFFFFFFu, dA, o);
            dB += __shfl_xor_sync(0xFFFFFFFFu, dB, o);
        }
        float wA = __expf(fmaxf(dA + C, 0.f));
        float wB = hasB ? __expf(fmaxf(dB + C, 0.f)) : 0.f;
        a0.x += wA*x0.x + wB*y0.x; a0.y += wA*x0.y + wB*y0.y;
        a0.z += wA*x0.z + wB*y0.z; a0.w += wA*x0.w + wB*y0.w;
        a1.x += wA*x1.x + wB*y1.x; a1.y += wA*x1.y + wB*y1.y;
        a1.z += wA*x1.z + wB*y1.z; a1.w += wA*x1.w + wB*y1.w;
        a2.x += wA*x2.x + wB*y2.x; a2.y += wA*x2.y + wB*y2.y;
        a2.z += wA*x2.z + wB*y2.z; a2.w += wA*x2.w + wB*y2.w;
        a3.x += wA*x3.x + wB*y3.x; a3.y += wA*x3.y + wB*y3.y;
        a3.z += wA*x3.z + wB*y3.z; a3.w += wA*x3.w + wB*y3.w;
        zloc += wA + wB;
    }
    __shared__ float zw[8];
    if (lane == 0) zw[w] = zloc;   // zloc identical across lanes

    int c = 4 * lane;
    atomicAdd(&scol[c + 0],       a0.x); atomicAdd(&scol[c + 1],       a0.y);
    atomicAdd(&scol[c + 2],       a0.z); atomicAdd(&scol[c + 3],       a0.w);
    atomicAdd(&scol[128 + c + 0], a1.x); atomicAdd(&scol[128 + c + 1], a1.y);
    atomicAdd(&scol[128 + c + 2], a1.z); atomicAdd(&scol[128 + c + 3], a1.w);
    atomicAdd(&scol[256 + c + 0], a2.x); atomicAdd(&scol[256 + c + 1], a2.y);
    atomicAdd(&scol[256 + c + 2], a2.z); atomicAdd(&scol[256 + c + 3], a2.w);
    atomicAdd(&scol[384 + c + 0], a3.x); atomicAdd(&scol[384 + c + 1], a3.y);
    atomicAdd(&scol[384 + c + 2], a3.z); atomicAdd(&scol[384 + c + 3], a3.w);
    __syncthreads();
    if (tid == 0) {
        float z = 0.f;
        #pragma unroll
        for (int q = 0; q < 8; q++) z += zw[q];
        atomicAdd(&g_scal[2], z);
    }
    for (int j = tid; j < M; j += 256) atomicAdd(&out[j], scol[j]);

    // last CTA: normalize by Z; cleanup for next graph replay
    __shared__ bool isLast;
    __threadfence();
    __syncthreads();
    if (tid == 0) isLast = (atomicAdd(&g_cnt2, 1u) == gridDim.x - 1);
    __syncthreads();
    if (isLast) {
        float invZ = 1.0f / g_scal[2];
        for (int j = tid; j < M; j += 256) out[j] *= invZ;
        if (tid == 0) { g_scal[2] = 0.f; g_cnt2 = 0u; }
    }
}

// ---------------------------------------------------------------------------
extern "C" void kernel_launch(void* const* d_in, const int* in_sizes, int n_in,
                              void* d_out, int out_size) {
    const float* x = (const float*)d_in[0];   // [K, 512]
    const float* W = (const float*)d_in[1];   // [512, 512]
    const float* b = (const float*)d_in[2];   // [512]
    const float* a = (const float*)d_in[3];   // [1024]
    float* out = (float*)d_out;               // [512]
    int K = in_sizes[0] / M;

    mhi_k1<<<K1_GRID, 256>>>(x, W, b, a, out, K);
    mhi_k2<<<K2_GRID, 256>>>(x, out, K);
}